// round 7
// baseline (speedup 1.0000x reference)
#include <cuda_runtime.h>
#include <cuda_fp16.h>
#include <cstdint>
#include <cstddef>

#define G_   128
#define M_   512
#define D_   512
#define MA   513
#define LD2  512          // dense E leading dim (no bins stored)
#define NORM_C (1.0f/1024.0f)

// ---------------- scratch ----------------
__device__ __align__(16) __half g_E[(size_t)G_ * M_ * LD2];   // exp(-c/lambda), 64 MB
__device__ __align__(16) __half g_Ah[(size_t)G_ * M_ * D_];   // normalized tra fp16
__device__ __align__(16) __half g_Bh[(size_t)G_ * M_ * D_];   // normalized det fp16

// ---------------- helpers ----------------
__device__ __forceinline__ uint32_t pack_h2(float lo, float hi) {
    uint32_t r; asm("cvt.rn.f16x2.f32 %0, %1, %2;" : "=r"(r) : "f"(hi), "f"(lo)); return r;
}
__device__ __forceinline__ uint32_t s2u(const void* p) {
    return (uint32_t)__cvta_generic_to_shared(p);
}
__device__ __forceinline__ void cp16(uint32_t saddr, const void* g) {
    asm volatile("cp.async.cg.shared.global [%0], [%1], 16;" :: "r"(saddr), "l"(g));
}
__device__ __forceinline__ void ldsm4(uint32_t* r, uint32_t a) {
    asm volatile("ldmatrix.sync.aligned.m8n8.x4.shared.b16 {%0,%1,%2,%3}, [%4];"
                 : "=r"(r[0]), "=r"(r[1]), "=r"(r[2]), "=r"(r[3]) : "r"(a));
}
__device__ __forceinline__ void ld_raw(const __half* Eg, int i, int lane, uint4& d0, uint4& d1) {
    const uint4* rp = reinterpret_cast<const uint4*>(Eg + (size_t)i * LD2) + lane * 2;
    d0 = rp[0]; d1 = rp[1];
}
__device__ __forceinline__ void cvt8(uint4 d0, uint4 d1, float2* e) {
    e[0] = __half22float2(*reinterpret_cast<__half2*>(&d0.x));
    e[1] = __half22float2(*reinterpret_cast<__half2*>(&d0.y));
    e[2] = __half22float2(*reinterpret_cast<__half2*>(&d0.z));
    e[3] = __half22float2(*reinterpret_cast<__half2*>(&d0.w));
    e[4] = __half22float2(*reinterpret_cast<__half2*>(&d1.x));
    e[5] = __half22float2(*reinterpret_cast<__half2*>(&d1.y));
    e[6] = __half22float2(*reinterpret_cast<__half2*>(&d1.z));
    e[7] = __half22float2(*reinterpret_cast<__half2*>(&d1.w));
}

// ---------------- normalize + fp16 convert ----------------
__global__ void __launch_bounds__(256) normalize_kernel(const float* __restrict__ tra,
                                                        const float* __restrict__ det) {
    const float* x = blockIdx.y ? det : tra;
    __half* out = blockIdx.y ? g_Bh : g_Ah;
    int warp = threadIdx.x >> 5, lane = threadIdx.x & 31;
    int row = blockIdx.x * 8 + warp;
    const float4* p = reinterpret_cast<const float4*>(x + (size_t)row * D_);
    float4 v[4];
    float s = 0.f;
#pragma unroll
    for (int k = 0; k < 4; ++k) {
        v[k] = p[lane + k * 32];
        s += v[k].x * v[k].x + v[k].y * v[k].y + v[k].z * v[k].z + v[k].w * v[k].w;
    }
#pragma unroll
    for (int o = 16; o > 0; o >>= 1) s += __shfl_xor_sync(0xffffffffu, s, o);
    float inv = rsqrtf(s);
    uint2* po = reinterpret_cast<uint2*>(out + (size_t)row * D_);
#pragma unroll
    for (int k = 0; k < 4; ++k) {
        uint2 h;
        h.x = pack_h2(v[k].x * inv, v[k].y * inv);
        h.y = pack_h2(v[k].z * inv, v[k].w * inv);
        po[lane + k * 32] = h;
    }
}

// ---------------- fp16 GEMM: 3-stage cp.async pipeline + exp epilogue ----------------
#define BK 32
#define ROWH 40
#define TILE_H (128 * ROWH)                 // halves per matrix per stage
#define STAGE_B (2 * TILE_H * 2)            // bytes per stage (A+B)
#define GEMM_SMEM (3 * STAGE_B)             // 61440 B

__global__ void __launch_bounds__(256) gemm_kernel(const float* __restrict__ eps) {
    extern __shared__ __half smem_g[];
    const int tid = threadIdx.x;
    const int lane = tid & 31, warp = tid >> 5;
    const int wm = warp >> 2, wn = warp & 3;
    const int grp = lane >> 2, tig = lane & 3;
    const int g = blockIdx.z;
    const int m0 = blockIdx.y * 128, n0 = blockIdx.x * 128;
    const __half* gA = g_Ah + (size_t)(g * M_ + m0) * D_;
    const __half* gB = g_Bh + (size_t)(g * M_ + n0) * D_;
    const uint32_t sbase = s2u(smem_g);

    const int aRow = (((lane >> 3) & 1) << 3) + (lane & 7);
    const int aCol = ((lane >> 4) << 3);
    const int bRow = ((lane >> 4) << 3) + (lane & 7);
    const int bCol = (((lane >> 3) & 1) << 3);

    float acc[4][4][4];
#pragma unroll
    for (int a = 0; a < 4; ++a)
#pragma unroll
        for (int b = 0; b < 4; ++b)
#pragma unroll
            for (int c = 0; c < 4; ++c) acc[a][b][c] = 0.f;

    const int lrow = tid >> 2, lc = tid & 3;
    auto load = [&](int kc, int st) {
        const __half* a = gA + kc * BK;
        const __half* b = gB + kc * BK;
        const uint32_t sa = sbase + st * STAGE_B;
        const uint32_t sb = sa + TILE_H * 2;
#pragma unroll
        for (int t = 0; t < 2; ++t) {
            int row = lrow + t * 64;
            cp16(sa + (row * ROWH + lc * 8) * 2, a + (size_t)row * D_ + lc * 8);
            cp16(sb + (row * ROWH + lc * 8) * 2, b + (size_t)row * D_ + lc * 8);
        }
        asm volatile("cp.async.commit_group;" ::: "memory");
    };

    load(0, 0);
    load(1, 1);
    const int NKT = D_ / BK;   // 16
    for (int kt = 0; kt < NKT; ++kt) {
        asm volatile("cp.async.wait_group 1;" ::: "memory");
        __syncthreads();
        if (kt + 2 < NKT) load(kt + 2, (kt + 2) % 3);
        const int st = kt % 3;
        const uint32_t ab = sbase + st * STAGE_B;
        const uint32_t bb = ab + TILE_H * 2;
#pragma unroll
        for (int ks = 0; ks < 2; ++ks) {
            uint32_t af[4][4], bf[2][4];
#pragma unroll
            for (int mt = 0; mt < 4; ++mt)
                ldsm4(af[mt], ab + ((wm * 64 + mt * 16 + aRow) * ROWH + ks * 16 + aCol) * 2);
#pragma unroll
            for (int p = 0; p < 2; ++p)
                ldsm4(bf[p], bb + ((wn * 32 + p * 16 + bRow) * ROWH + ks * 16 + bCol) * 2);
#pragma unroll
            for (int mt = 0; mt < 4; ++mt)
#pragma unroll
                for (int nt = 0; nt < 4; ++nt)
                    asm volatile(
                        "mma.sync.aligned.m16n8k16.row.col.f32.f16.f16.f32 "
                        "{%0,%1,%2,%3}, {%4,%5,%6,%7}, {%8,%9}, {%0,%1,%2,%3};"
                        : "+f"(acc[mt][nt][0]), "+f"(acc[mt][nt][1]),
                          "+f"(acc[mt][nt][2]), "+f"(acc[mt][nt][3])
                        : "r"(af[mt][0]), "r"(af[mt][1]), "r"(af[mt][2]), "r"(af[mt][3]),
                          "r"(bf[nt >> 1][(nt & 1) * 2]), "r"(bf[nt >> 1][(nt & 1) * 2 + 1]));
        }
        __syncthreads();
    }

    const float invL = 1.0f / (__expf(eps[0]) + 0.03f);
    __half* Eg = g_E + (size_t)g * M_ * LD2;
#pragma unroll
    for (int mt = 0; mt < 4; ++mt) {
        int m = m0 + wm * 64 + mt * 16 + grp;
#pragma unroll
        for (int nt = 0; nt < 4; ++nt) {
            int n = n0 + wn * 32 + nt * 8 + 2 * tig;
            uint32_t r0 = pack_h2(__expf(-acc[mt][nt][0] * invL),
                                  __expf(-acc[mt][nt][1] * invL));
            uint32_t r1 = pack_h2(__expf(-acc[mt][nt][2] * invL),
                                  __expf(-acc[mt][nt][3] * invL));
            *reinterpret_cast<uint32_t*>(&Eg[(size_t)m * LD2 + n])       = r0;
            *reinterpret_cast<uint32_t*>(&Eg[(size_t)(m + 8) * LD2 + n]) = r1;
        }
    }
}

// ---------------- fused Sinkhorn: 9 E-passes, bins analytic, pipelined loads ----------------
#define SH_SV    0
#define SH_WSUM  520
#define SH_SCAL  552
#define SH_COL   560
#define SH_FLOATS (560 + 32 * 512)

__global__ void __launch_bounds__(1024, 1) sinkhorn_kernel(
    float* __restrict__ out, const float* __restrict__ alpha, const float* __restrict__ eps)
{
    extern __shared__ float sh[];
    float* sv    = sh + SH_SV;
    float* swsum = sh + SH_WSUM;
    float* sscal = sh + SH_SCAL;
    float* scol  = sh + SH_COL;
    const int g = blockIdx.x, tid = threadIdx.x, w = tid >> 5, lane = tid & 31;
    const __half* Eg = g_E + (size_t)g * M_ * LD2;
    const float invL = 1.f / (__expf(eps[0]) + 0.03f);
    const float c = __expf(-alpha[0] * invL);
    const float AB512 = NORM_C * 512.f;
    const int row0 = w * 16;
    float2 e[8];
    uint4 c0, c1, n0, n1;

    // ---- pass 0: column sums with u == 1 ----
    {
        float2 ca[8];
#pragma unroll
        for (int q = 0; q < 8; ++q) ca[q] = make_float2(0.f, 0.f);
        ld_raw(Eg, row0, lane, c0, c1);
#pragma unroll
        for (int t = 0; t < 16; ++t) {
            if (t < 15) ld_raw(Eg, row0 + t + 1, lane, n0, n1);
            cvt8(c0, c1, e);
#pragma unroll
            for (int q = 0; q < 8; ++q) { ca[q].x += e[q].x; ca[q].y += e[q].y; }
            c0 = n0; c1 = n1;
        }
        float* dst = scol + w * 512 + lane * 16;
#pragma unroll
        for (int q = 0; q < 8; ++q) { dst[2 * q] = ca[q].x; dst[2 * q + 1] = ca[q].y; }
    }
    __syncthreads();
    if (tid < 512) {
        float s = c;
#pragma unroll
        for (int ww = 0; ww < 32; ++ww) s += scol[ww * 512 + tid];
        sv[tid] = NORM_C / s;
    } else if (tid == 512) {
        sv[512] = AB512 / (c * 513.f);
    }
    __syncthreads();
    if (w == 0) {
        float p = 0.f;
#pragma unroll
        for (int k = 0; k < 16; ++k) p += sv[lane + 32 * k];
#pragma unroll
        for (int o = 16; o > 0; o >>= 1) p += __shfl_xor_sync(0xffffffffu, p, o);
        if (lane == 0) sscal[0] = AB512 / (c * (p + sv[512]));
    }
    __syncthreads();

    // ---- 7 fused passes ----
    for (int it = 0; it < 7; ++it) {
        float2 vr[8];
#pragma unroll
        for (int q = 0; q < 8; ++q) vr[q] = *reinterpret_cast<float2*>(&sv[lane * 16 + 2 * q]);
        const float v512 = sv[512];
        const float u512 = sscal[0];
        float2 ca[8];
#pragma unroll
        for (int q = 0; q < 8; ++q) ca[q] = make_float2(0.f, 0.f);
        float wsum = 0.f;
        ld_raw(Eg, row0, lane, c0, c1);
#pragma unroll 4
        for (int t = 0; t < 16; ++t) {
            if (t < 15) ld_raw(Eg, row0 + t + 1, lane, n0, n1);
            cvt8(c0, c1, e);
            float rs = 0.f;
#pragma unroll
            for (int q = 0; q < 8; ++q) rs += e[q].x * vr[q].x + e[q].y * vr[q].y;
#pragma unroll
            for (int o = 16; o > 0; o >>= 1) rs += __shfl_xor_sync(0xffffffffu, rs, o);
            float u = NORM_C / (rs + c * v512);
            wsum += u;
#pragma unroll
            for (int q = 0; q < 8; ++q) { ca[q].x += u * e[q].x; ca[q].y += u * e[q].y; }
            c0 = n0; c1 = n1;
        }
        {
            float* dst = scol + w * 512 + lane * 16;
#pragma unroll
            for (int q = 0; q < 8; ++q) { dst[2 * q] = ca[q].x; dst[2 * q + 1] = ca[q].y; }
        }
        if (lane == 0) swsum[w] = wsum;
        __syncthreads();
        if (tid < 512) {
            float s = c * u512;
#pragma unroll
            for (int ww = 0; ww < 32; ++ww) s += scol[ww * 512 + tid];
            sv[tid] = NORM_C / s;
        } else if (tid == 512) {
            float sU = u512;
#pragma unroll
            for (int ww = 0; ww < 32; ++ww) sU += swsum[ww];
            sv[512] = AB512 / (c * sU);
        }
        __syncthreads();
        if (w == 0) {
            float p = 0.f;
#pragma unroll
            for (int k = 0; k < 16; ++k) p += sv[lane + 32 * k];
#pragma unroll
            for (int o = 16; o > 0; o >>= 1) p += __shfl_xor_sync(0xffffffffu, p, o);
            if (lane == 0) sscal[0] = AB512 / (c * (p + sv[512]));
        }
        __syncthreads();
    }

    // ---- final pass: u_8 + output write ----
    {
        float2 vr[8];
#pragma unroll
        for (int q = 0; q < 8; ++q) vr[q] = *reinterpret_cast<float2*>(&sv[lane * 16 + 2 * q]);
        const float v512 = sv[512];
        const float u512 = sscal[0];
        float* og = out + (size_t)g * MA * MA;
        ld_raw(Eg, row0, lane, c0, c1);
#pragma unroll 2
        for (int t = 0; t < 16; ++t) {
            int i = row0 + t;
            if (t < 15) ld_raw(Eg, i + 1, lane, n0, n1);
            cvt8(c0, c1, e);
            float rs = 0.f;
#pragma unroll
            for (int q = 0; q < 8; ++q) rs += e[q].x * vr[q].x + e[q].y * vr[q].y;
#pragma unroll
            for (int o = 16; o > 0; o >>= 1) rs += __shfl_xor_sync(0xffffffffu, rs, o);
            float u = NORM_C / (rs + c * v512);
            float* orow = og + (size_t)i * MA + lane * 16;
#pragma unroll
            for (int q = 0; q < 8; ++q) {
                orow[2 * q]     = u * e[q].x * vr[q].x;
                orow[2 * q + 1] = u * e[q].y * vr[q].y;
            }
            if (lane == 0) og[(size_t)i * MA + 512] = u * c * v512;
            c0 = n0; c1 = n1;
        }
        for (int j = tid; j < 512; j += 1024)
            og[(size_t)512 * MA + j] = u512 * c * sv[j];
        if (tid == 0) og[(size_t)512 * MA + 512] = u512 * c * v512;
    }
}

// ---------------- launch ----------------
extern "C" void kernel_launch(void* const* d_in, const int* in_sizes, int n_in,
                              void* d_out, int out_size) {
    const float* det   = (const float*)d_in[0];
    const float* tra   = (const float*)d_in[1];
    const float* alpha = (const float*)d_in[2];
    const float* eps   = (const float*)d_in[3];
    float* out = (float*)d_out;

    cudaFuncSetAttribute(sinkhorn_kernel, cudaFuncAttributeMaxDynamicSharedMemorySize,
                         SH_FLOATS * (int)sizeof(float));
    cudaFuncSetAttribute(gemm_kernel, cudaFuncAttributeMaxDynamicSharedMemorySize, GEMM_SMEM);

    normalize_kernel<<<dim3((G_ * M_) / 8, 2), 256>>>(tra, det);
    gemm_kernel<<<dim3(4, 4, G_), 256, GEMM_SMEM>>>(eps);
    sinkhorn_kernel<<<G_, 1024, SH_FLOATS * sizeof(float)>>>(out, alpha, eps);
}

// round 8
// speedup vs baseline: 1.1208x; 1.1208x over previous
#include <cuda_runtime.h>
#include <cuda_fp16.h>
#include <cstdint>
#include <cstddef>

#define G_   128
#define M_   512
#define D_   512
#define MA   513
#define LD2  512          // dense E leading dim (no bins stored)
#define NORM_C (1.0f/1024.0f)

// ---------------- scratch ----------------
__device__ __align__(16) __half g_E[(size_t)G_ * M_ * LD2];   // exp(-c/lambda), 64 MB
__device__ __align__(16) __half g_Ah[(size_t)G_ * M_ * D_];   // normalized tra fp16
__device__ __align__(16) __half g_Bh[(size_t)G_ * M_ * D_];   // normalized det fp16

// ---------------- helpers ----------------
__device__ __forceinline__ uint32_t pack_h2(float lo, float hi) {
    uint32_t r; asm("cvt.rn.f16x2.f32 %0, %1, %2;" : "=r"(r) : "f"(hi), "f"(lo)); return r;
}
__device__ __forceinline__ uint32_t s2u(const void* p) {
    return (uint32_t)__cvta_generic_to_shared(p);
}
__device__ __forceinline__ void cp16(uint32_t saddr, const void* g) {
    asm volatile("cp.async.cg.shared.global [%0], [%1], 16;" :: "r"(saddr), "l"(g));
}
__device__ __forceinline__ void ldsm4(uint32_t* r, uint32_t a) {
    asm volatile("ldmatrix.sync.aligned.m8n8.x4.shared.b16 {%0,%1,%2,%3}, [%4];"
                 : "=r"(r[0]), "=r"(r[1]), "=r"(r[2]), "=r"(r[3]) : "r"(a));
}
__device__ __forceinline__ void ld_raw(const __half* Eg, int i, int lane, uint4& d0, uint4& d1) {
    const uint4* rp = reinterpret_cast<const uint4*>(Eg + (size_t)i * LD2) + lane * 2;
    d0 = rp[0]; d1 = rp[1];
}
__device__ __forceinline__ void cvt8(uint4 d0, uint4 d1, float2* e) {
    e[0] = __half22float2(*reinterpret_cast<__half2*>(&d0.x));
    e[1] = __half22float2(*reinterpret_cast<__half2*>(&d0.y));
    e[2] = __half22float2(*reinterpret_cast<__half2*>(&d0.z));
    e[3] = __half22float2(*reinterpret_cast<__half2*>(&d0.w));
    e[4] = __half22float2(*reinterpret_cast<__half2*>(&d1.x));
    e[5] = __half22float2(*reinterpret_cast<__half2*>(&d1.y));
    e[6] = __half22float2(*reinterpret_cast<__half2*>(&d1.z));
    e[7] = __half22float2(*reinterpret_cast<__half2*>(&d1.w));
}

// ---------------- normalize + fp16 convert ----------------
__global__ void __launch_bounds__(256) normalize_kernel(const float* __restrict__ tra,
                                                        const float* __restrict__ det) {
    const float* x = blockIdx.y ? det : tra;
    __half* out = blockIdx.y ? g_Bh : g_Ah;
    int warp = threadIdx.x >> 5, lane = threadIdx.x & 31;
    int row = blockIdx.x * 8 + warp;
    const float4* p = reinterpret_cast<const float4*>(x + (size_t)row * D_);
    float4 v[4];
    float s = 0.f;
#pragma unroll
    for (int k = 0; k < 4; ++k) {
        v[k] = p[lane + k * 32];
        s += v[k].x * v[k].x + v[k].y * v[k].y + v[k].z * v[k].z + v[k].w * v[k].w;
    }
#pragma unroll
    for (int o = 16; o > 0; o >>= 1) s += __shfl_xor_sync(0xffffffffu, s, o);
    float inv = rsqrtf(s);
    uint2* po = reinterpret_cast<uint2*>(out + (size_t)row * D_);
#pragma unroll
    for (int k = 0; k < 4; ++k) {
        uint2 h;
        h.x = pack_h2(v[k].x * inv, v[k].y * inv);
        h.y = pack_h2(v[k].z * inv, v[k].w * inv);
        po[lane + k * 32] = h;
    }
}

// ---------------- fp16 GEMM (ldmatrix + mma.sync m16n8k16) + exp epilogue ----------------
#define BK 32
#define ROWH 40
#define TILE_H (128 * ROWH)

__global__ void __launch_bounds__(256) gemm_kernel(const float* __restrict__ eps) {
    __shared__ __half sA[2][TILE_H];
    __shared__ __half sB[2][TILE_H];
    const int tid = threadIdx.x;
    const int lane = tid & 31, warp = tid >> 5;
    const int wm = warp >> 2, wn = warp & 3;
    const int grp = lane >> 2, tig = lane & 3;
    const int g = blockIdx.z;
    const int m0 = blockIdx.y * 128, n0 = blockIdx.x * 128;
    const __half* gA = g_Ah + (size_t)(g * M_ + m0) * D_;
    const __half* gB = g_Bh + (size_t)(g * M_ + n0) * D_;
    const uint32_t sAu = s2u(sA), sBu = s2u(sB);

    const int aRow = (((lane >> 3) & 1) << 3) + (lane & 7);
    const int aCol = ((lane >> 4) << 3);
    const int bRow = ((lane >> 4) << 3) + (lane & 7);
    const int bCol = (((lane >> 3) & 1) << 3);

    float acc[4][4][4];
#pragma unroll
    for (int a = 0; a < 4; ++a)
#pragma unroll
        for (int b = 0; b < 4; ++b)
#pragma unroll
            for (int c = 0; c < 4; ++c) acc[a][b][c] = 0.f;

    const int lrow = tid >> 2, lc = tid & 3;
    auto load = [&](int kc, int buf) {
        const __half* a = gA + kc * BK;
        const __half* b = gB + kc * BK;
#pragma unroll
        for (int t = 0; t < 2; ++t) {
            int row = lrow + t * 64;
            cp16(sAu + (buf * TILE_H + row * ROWH) * 2 + lc * 16, a + (size_t)row * D_ + lc * 8);
            cp16(sBu + (buf * TILE_H + row * ROWH) * 2 + lc * 16, b + (size_t)row * D_ + lc * 8);
        }
        asm volatile("cp.async.commit_group;" ::: "memory");
    };

    load(0, 0);
    const int NKT = D_ / BK;
    for (int kt = 0; kt < NKT; ++kt) {
        asm volatile("cp.async.wait_group 0;" ::: "memory");
        __syncthreads();
        if (kt + 1 < NKT) load(kt + 1, (kt + 1) & 1);
        const int buf = kt & 1;
        const uint32_t ab = sAu + (buf * TILE_H) * 2;
        const uint32_t bb = sBu + (buf * TILE_H) * 2;
#pragma unroll
        for (int ks = 0; ks < 2; ++ks) {
            uint32_t af[4][4], bf[2][4];
#pragma unroll
            for (int mt = 0; mt < 4; ++mt)
                ldsm4(af[mt], ab + ((wm * 64 + mt * 16 + aRow) * ROWH + ks * 16 + aCol) * 2);
#pragma unroll
            for (int p = 0; p < 2; ++p)
                ldsm4(bf[p], bb + ((wn * 32 + p * 16 + bRow) * ROWH + ks * 16 + bCol) * 2);
#pragma unroll
            for (int mt = 0; mt < 4; ++mt)
#pragma unroll
                for (int nt = 0; nt < 4; ++nt)
                    asm volatile(
                        "mma.sync.aligned.m16n8k16.row.col.f32.f16.f16.f32 "
                        "{%0,%1,%2,%3}, {%4,%5,%6,%7}, {%8,%9}, {%0,%1,%2,%3};"
                        : "+f"(acc[mt][nt][0]), "+f"(acc[mt][nt][1]),
                          "+f"(acc[mt][nt][2]), "+f"(acc[mt][nt][3])
                        : "r"(af[mt][0]), "r"(af[mt][1]), "r"(af[mt][2]), "r"(af[mt][3]),
                          "r"(bf[nt >> 1][(nt & 1) * 2]), "r"(bf[nt >> 1][(nt & 1) * 2 + 1]));
        }
    }

    const float invL = 1.0f / (__expf(eps[0]) + 0.03f);
    __half* Eg = g_E + (size_t)g * M_ * LD2;
#pragma unroll
    for (int mt = 0; mt < 4; ++mt) {
        int m = m0 + wm * 64 + mt * 16 + grp;
#pragma unroll
        for (int nt = 0; nt < 4; ++nt) {
            int n = n0 + wn * 32 + nt * 8 + 2 * tig;
            uint32_t r0 = pack_h2(__expf(-acc[mt][nt][0] * invL),
                                  __expf(-acc[mt][nt][1] * invL));
            uint32_t r1 = pack_h2(__expf(-acc[mt][nt][2] * invL),
                                  __expf(-acc[mt][nt][3] * invL));
            *reinterpret_cast<uint32_t*>(&Eg[(size_t)m * LD2 + n])       = r0;
            *reinterpret_cast<uint32_t*>(&Eg[(size_t)(m + 8) * LD2 + n]) = r1;
        }
    }
}

// ---------------- fused Sinkhorn: 9 E-passes, bins analytic, 512 thr (no spills) ----------------
// smem: sv[520] | swsum[16] | sscal[8] | scol[16*512]
#define SH_SV    0
#define SH_WSUM  520
#define SH_SCAL  536
#define SH_COL   544
#define SH_FLOATS (544 + 16 * 512)

__global__ void __launch_bounds__(512, 1) sinkhorn_kernel(
    float* __restrict__ out, const float* __restrict__ alpha, const float* __restrict__ eps)
{
    extern __shared__ float sh[];
    float* sv    = sh + SH_SV;
    float* swsum = sh + SH_WSUM;
    float* sscal = sh + SH_SCAL;
    float* scol  = sh + SH_COL;
    const int g = blockIdx.x, tid = threadIdx.x, w = tid >> 5, lane = tid & 31;
    const __half* Eg = g_E + (size_t)g * M_ * LD2;
    const float invL = 1.f / (__expf(eps[0]) + 0.03f);
    const float c = __expf(-alpha[0] * invL);
    const float AB512 = NORM_C * 512.f;
    const int row0 = w * 32;
    float2 e[8];
    uint4 c0, c1, n0, n1;

    // ---- pass 0: column sums with u == 1 ----
    {
        float2 ca[8];
#pragma unroll
        for (int q = 0; q < 8; ++q) ca[q] = make_float2(0.f, 0.f);
        ld_raw(Eg, row0, lane, c0, c1);
#pragma unroll 4
        for (int t = 0; t < 32; ++t) {
            if (t < 31) ld_raw(Eg, row0 + t + 1, lane, n0, n1);
            cvt8(c0, c1, e);
#pragma unroll
            for (int q = 0; q < 8; ++q) { ca[q].x += e[q].x; ca[q].y += e[q].y; }
            c0 = n0; c1 = n1;
        }
        float* dst = scol + w * 512 + lane * 16;
#pragma unroll
        for (int q = 0; q < 8; ++q) { dst[2 * q] = ca[q].x; dst[2 * q + 1] = ca[q].y; }
    }
    __syncthreads();
    {
        float s = c;                          // bin-row contribution, u512 = 1
#pragma unroll
        for (int ww = 0; ww < 16; ++ww) s += scol[ww * 512 + tid];
        sv[tid] = NORM_C / s;
        if (tid == 0) sv[512] = AB512 / (c * 513.f);   // colsum_512 = c * 513
    }
    __syncthreads();
    if (w == 0) {                             // sumV -> u512
        float p = 0.f;
#pragma unroll
        for (int k = 0; k < 16; ++k) p += sv[lane + 32 * k];
#pragma unroll
        for (int o = 16; o > 0; o >>= 1) p += __shfl_xor_sync(0xffffffffu, p, o);
        if (lane == 0) sscal[0] = AB512 / (c * (p + sv[512]));
    }
    __syncthreads();

    // ---- 7 fused passes: row update k + col accumulation k+1, one E read ----
    for (int it = 0; it < 7; ++it) {
        float2 vr[8];
#pragma unroll
        for (int q = 0; q < 8; ++q) vr[q] = *reinterpret_cast<float2*>(&sv[lane * 16 + 2 * q]);
        const float v512 = sv[512];
        const float u512 = sscal[0];
        float2 ca[8];
#pragma unroll
        for (int q = 0; q < 8; ++q) ca[q] = make_float2(0.f, 0.f);
        float wsum = 0.f;
        ld_raw(Eg, row0, lane, c0, c1);
#pragma unroll 4
        for (int t = 0; t < 32; ++t) {
            if (t < 31) ld_raw(Eg, row0 + t + 1, lane, n0, n1);
            cvt8(c0, c1, e);
            float rs = 0.f;
#pragma unroll
            for (int q = 0; q < 8; ++q) rs += e[q].x * vr[q].x + e[q].y * vr[q].y;
#pragma unroll
            for (int o = 16; o > 0; o >>= 1) rs += __shfl_xor_sync(0xffffffffu, rs, o);
            float u = NORM_C / (rs + c * v512);
            wsum += u;
#pragma unroll
            for (int q = 0; q < 8; ++q) { ca[q].x += u * e[q].x; ca[q].y += u * e[q].y; }
            c0 = n0; c1 = n1;
        }
        {
            float* dst = scol + w * 512 + lane * 16;
#pragma unroll
            for (int q = 0; q < 8; ++q) { dst[2 * q] = ca[q].x; dst[2 * q + 1] = ca[q].y; }
        }
        if (lane == 0) swsum[w] = wsum;
        __syncthreads();
        {
            float s = c * u512;
#pragma unroll
            for (int ww = 0; ww < 16; ++ww) s += scol[ww * 512 + tid];
            sv[tid] = NORM_C / s;
            if (tid == 0) {
                float sU = u512;
#pragma unroll
                for (int ww = 0; ww < 16; ++ww) sU += swsum[ww];
                sv[512] = AB512 / (c * sU);
            }
        }
        __syncthreads();
        if (w == 0) {
            float p = 0.f;
#pragma unroll
            for (int k = 0; k < 16; ++k) p += sv[lane + 32 * k];
#pragma unroll
            for (int o = 16; o > 0; o >>= 1) p += __shfl_xor_sync(0xffffffffu, p, o);
            if (lane == 0) sscal[0] = AB512 / (c * (p + sv[512]));
        }
        __syncthreads();
    }

    // ---- final pass: u_8 + output write in one E read ----
    {
        float2 vr[8];
#pragma unroll
        for (int q = 0; q < 8; ++q) vr[q] = *reinterpret_cast<float2*>(&sv[lane * 16 + 2 * q]);
        const float v512 = sv[512];
        const float u512 = sscal[0];
        float* og = out + (size_t)g * MA * MA;
        ld_raw(Eg, row0, lane, c0, c1);
#pragma unroll 2
        for (int t = 0; t < 32; ++t) {
            int i = row0 + t;
            if (t < 31) ld_raw(Eg, i + 1, lane, n0, n1);
            cvt8(c0, c1, e);
            float rs = 0.f;
#pragma unroll
            for (int q = 0; q < 8; ++q) rs += e[q].x * vr[q].x + e[q].y * vr[q].y;
#pragma unroll
            for (int o = 16; o > 0; o >>= 1) rs += __shfl_xor_sync(0xffffffffu, rs, o);
            float u = NORM_C / (rs + c * v512);
            float* orow = og + (size_t)i * MA + lane * 16;
#pragma unroll
            for (int q = 0; q < 8; ++q) {
                orow[2 * q]     = u * e[q].x * vr[q].x;
                orow[2 * q + 1] = u * e[q].y * vr[q].y;
            }
            if (lane == 0) og[(size_t)i * MA + 512] = u * c * v512;
            c0 = n0; c1 = n1;
        }
        og[(size_t)512 * MA + tid] = u512 * c * sv[tid];
        if (tid == 0) og[(size_t)512 * MA + 512] = u512 * c * v512;
    }
}

// ---------------- launch ----------------
extern "C" void kernel_launch(void* const* d_in, const int* in_sizes, int n_in,
                              void* d_out, int out_size) {
    const float* det   = (const float*)d_in[0];
    const float* tra   = (const float*)d_in[1];
    const float* alpha = (const float*)d_in[2];
    const float* eps   = (const float*)d_in[3];
    float* out = (float*)d_out;

    cudaFuncSetAttribute(sinkhorn_kernel, cudaFuncAttributeMaxDynamicSharedMemorySize,
                         SH_FLOATS * (int)sizeof(float));

    normalize_kernel<<<dim3((G_ * M_) / 8, 2), 256>>>(tra, det);
    gemm_kernel<<<dim3(4, 4, G_), 256>>>(eps);
    sinkhorn_kernel<<<G_, 512, SH_FLOATS * sizeof(float)>>>(out, alpha, eps);
}

// round 10
// speedup vs baseline: 1.1366x; 1.0141x over previous
#include <cuda_runtime.h>
#include <cuda_fp16.h>
#include <cstdint>
#include <cstddef>

#define G_   128
#define M_   512
#define D_   512
#define MA   513
#define LD2  512
#define NORM_C (1.0f/1024.0f)

// ---------------- scratch ----------------
__device__ __align__(16) __half g_E[(size_t)G_ * M_ * LD2];   // exp(-c/lambda), 64 MB
__device__ __align__(16) __half g_Ah[(size_t)G_ * M_ * D_];   // normalized tra fp16
__device__ __align__(16) __half g_Bh[(size_t)G_ * M_ * D_];   // normalized det fp16

// ---------------- helpers ----------------
__device__ __forceinline__ uint32_t pack_h2(float lo, float hi) {
    uint32_t r; asm("cvt.rn.f16x2.f32 %0, %1, %2;" : "=r"(r) : "f"(hi), "f"(lo)); return r;
}
__device__ __forceinline__ uint32_t s2u(const void* p) {
    return (uint32_t)__cvta_generic_to_shared(p);
}
__device__ __forceinline__ void cp16(uint32_t saddr, const void* g) {
    asm volatile("cp.async.cg.shared.global [%0], [%1], 16;" :: "r"(saddr), "l"(g));
}
__device__ __forceinline__ void ldsm4(uint32_t* r, uint32_t a) {
    asm volatile("ldmatrix.sync.aligned.m8n8.x4.shared.b16 {%0,%1,%2,%3}, [%4];"
                 : "=r"(r[0]), "=r"(r[1]), "=r"(r[2]), "=r"(r[3]) : "r"(a));
}
__device__ __forceinline__ void cvt8(uint4 d0, uint4 d1, float2* e) {
    e[0] = __half22float2(*reinterpret_cast<__half2*>(&d0.x));
    e[1] = __half22float2(*reinterpret_cast<__half2*>(&d0.y));
    e[2] = __half22float2(*reinterpret_cast<__half2*>(&d0.z));
    e[3] = __half22float2(*reinterpret_cast<__half2*>(&d0.w));
    e[4] = __half22float2(*reinterpret_cast<__half2*>(&d1.x));
    e[5] = __half22float2(*reinterpret_cast<__half2*>(&d1.y));
    e[6] = __half22float2(*reinterpret_cast<__half2*>(&d1.z));
    e[7] = __half22float2(*reinterpret_cast<__half2*>(&d1.w));
}

// ---------------- normalize + fp16 convert ----------------
__global__ void __launch_bounds__(256) normalize_kernel(const float* __restrict__ tra,
                                                        const float* __restrict__ det) {
    const float* x = blockIdx.y ? det : tra;
    __half* out = blockIdx.y ? g_Bh : g_Ah;
    int warp = threadIdx.x >> 5, lane = threadIdx.x & 31;
    int row = blockIdx.x * 8 + warp;
    const float4* p = reinterpret_cast<const float4*>(x + (size_t)row * D_);
    float4 v[4];
    float s = 0.f;
#pragma unroll
    for (int k = 0; k < 4; ++k) {
        v[k] = p[lane + k * 32];
        s += v[k].x * v[k].x + v[k].y * v[k].y + v[k].z * v[k].z + v[k].w * v[k].w;
    }
#pragma unroll
    for (int o = 16; o > 0; o >>= 1) s += __shfl_xor_sync(0xffffffffu, s, o);
    float inv = rsqrtf(s);
    uint2* po = reinterpret_cast<uint2*>(out + (size_t)row * D_);
#pragma unroll
    for (int k = 0; k < 4; ++k) {
        uint2 h;
        h.x = pack_h2(v[k].x * inv, v[k].y * inv);
        h.y = pack_h2(v[k].z * inv, v[k].w * inv);
        po[lane + k * 32] = h;
    }
}

// ---------------- fp16 GEMM (ldmatrix + mma.sync m16n8k16) + exp epilogue ----------------
#define BK 32
#define ROWH 40
#define TILE_H (128 * ROWH)

__global__ void __launch_bounds__(256) gemm_kernel(const float* __restrict__ eps) {
    __shared__ __half sA[2][TILE_H];
    __shared__ __half sB[2][TILE_H];
    const int tid = threadIdx.x;
    const int lane = tid & 31, warp = tid >> 5;
    const int wm = warp >> 2, wn = warp & 3;
    const int grp = lane >> 2, tig = lane & 3;
    const int g = blockIdx.z;
    const int m0 = blockIdx.y * 128, n0 = blockIdx.x * 128;
    const __half* gA = g_Ah + (size_t)(g * M_ + m0) * D_;
    const __half* gB = g_Bh + (size_t)(g * M_ + n0) * D_;
    const uint32_t sAu = s2u(sA), sBu = s2u(sB);

    const int aRow = (((lane >> 3) & 1) << 3) + (lane & 7);
    const int aCol = ((lane >> 4) << 3);
    const int bRow = ((lane >> 4) << 3) + (lane & 7);
    const int bCol = (((lane >> 3) & 1) << 3);

    float acc[4][4][4];
#pragma unroll
    for (int a = 0; a < 4; ++a)
#pragma unroll
        for (int b = 0; b < 4; ++b)
#pragma unroll
            for (int c = 0; c < 4; ++c) acc[a][b][c] = 0.f;

    const int lrow = tid >> 2, lc = tid & 3;
    auto load = [&](int kc, int buf) {
        const __half* a = gA + kc * BK;
        const __half* b = gB + kc * BK;
#pragma unroll
        for (int t = 0; t < 2; ++t) {
            int row = lrow + t * 64;
            cp16(sAu + (buf * TILE_H + row * ROWH) * 2 + lc * 16, a + (size_t)row * D_ + lc * 8);
            cp16(sBu + (buf * TILE_H + row * ROWH) * 2 + lc * 16, b + (size_t)row * D_ + lc * 8);
        }
        asm volatile("cp.async.commit_group;" ::: "memory");
    };

    load(0, 0);
    const int NKT = D_ / BK;
    for (int kt = 0; kt < NKT; ++kt) {
        asm volatile("cp.async.wait_group 0;" ::: "memory");
        __syncthreads();
        if (kt + 1 < NKT) load(kt + 1, (kt + 1) & 1);
        const int buf = kt & 1;
        const uint32_t ab = sAu + (buf * TILE_H) * 2;
        const uint32_t bb = sBu + (buf * TILE_H) * 2;
#pragma unroll
        for (int ks = 0; ks < 2; ++ks) {
            uint32_t af[4][4], bf[2][4];
#pragma unroll
            for (int mt = 0; mt < 4; ++mt)
                ldsm4(af[mt], ab + ((wm * 64 + mt * 16 + aRow) * ROWH + ks * 16 + aCol) * 2);
#pragma unroll
            for (int p = 0; p < 2; ++p)
                ldsm4(bf[p], bb + ((wn * 32 + p * 16 + bRow) * ROWH + ks * 16 + bCol) * 2);
#pragma unroll
            for (int mt = 0; mt < 4; ++mt)
#pragma unroll
                for (int nt = 0; nt < 4; ++nt)
                    asm volatile(
                        "mma.sync.aligned.m16n8k16.row.col.f32.f16.f16.f32 "
                        "{%0,%1,%2,%3}, {%4,%5,%6,%7}, {%8,%9}, {%0,%1,%2,%3};"
                        : "+f"(acc[mt][nt][0]), "+f"(acc[mt][nt][1]),
                          "+f"(acc[mt][nt][2]), "+f"(acc[mt][nt][3])
                        : "r"(af[mt][0]), "r"(af[mt][1]), "r"(af[mt][2]), "r"(af[mt][3]),
                          "r"(bf[nt >> 1][(nt & 1) * 2]), "r"(bf[nt >> 1][(nt & 1) * 2 + 1]));
        }
    }

    const float invL = 1.0f / (__expf(eps[0]) + 0.03f);
    __half* Eg = g_E + (size_t)g * M_ * LD2;
#pragma unroll
    for (int mt = 0; mt < 4; ++mt) {
        int m = m0 + wm * 64 + mt * 16 + grp;
#pragma unroll
        for (int nt = 0; nt < 4; ++nt) {
            int n = n0 + wn * 32 + nt * 8 + 2 * tig;
            uint32_t r0 = pack_h2(__expf(-acc[mt][nt][0] * invL),
                                  __expf(-acc[mt][nt][1] * invL));
            uint32_t r1 = pack_h2(__expf(-acc[mt][nt][2] * invL),
                                  __expf(-acc[mt][nt][3] * invL));
            *reinterpret_cast<uint32_t*>(&Eg[(size_t)m * LD2 + n])       = r0;
            *reinterpret_cast<uint32_t*>(&Eg[(size_t)(m + 8) * LD2 + n]) = r1;
        }
    }
}

// ---------------- fused Sinkhorn: cp.async-staged E, 4-row batches ----------------
// Thread column ownership: cols [lane*8, lane*8+8) and [256+lane*8, 256+lane*8+8)
// smem floats: sv[520] | swsum[16] | sscal[8] | scol[16*512] | stage[16 warps][2][1024]
#define SH_SV    0
#define SH_WSUM  520
#define SH_SCAL  536
#define SH_COL   544
#define SH_STAGE (544 + 16 * 512)
#define SH_FLOATS (SH_STAGE + 16 * 2 * 1024)

__global__ void __launch_bounds__(512, 1) sinkhorn_kernel(
    float* __restrict__ out, const float* __restrict__ alpha, const float* __restrict__ eps)
{
    extern __shared__ float sh[];
    float* sv    = sh + SH_SV;
    float* swsum = sh + SH_WSUM;
    float* sscal = sh + SH_SCAL;
    float* scol  = sh + SH_COL;
    const int g = blockIdx.x, tid = threadIdx.x, w = tid >> 5, lane = tid & 31;
    const __half* Eg = g_E + (size_t)g * M_ * LD2;
    const float invL = 1.f / (__expf(eps[0]) + 0.03f);
    const float c = __expf(-alpha[0] * invL);
    const float AB512 = NORM_C * 512.f;
    const int row0 = w * 32;
    float* stage = sh + SH_STAGE + w * 2048;          // 2 bufs x 1024 floats (4 rows each)
    const uint32_t stage_u = s2u(stage);

    // issue 4-row batch b into buffer b&1
    auto issue_batch = [&](int b) {
        const char* src = reinterpret_cast<const char*>(Eg + (size_t)(row0 + b * 4) * LD2);
        const uint32_t dst = stage_u + (b & 1) * 4096;
#pragma unroll
        for (int j = 0; j < 8; ++j)
            cp16(dst + j * 512 + lane * 16, src + j * 512 + lane * 16);
        asm volatile("cp.async.commit_group;" ::: "memory");
    };
    // read staged row r (0..3) of buffer buf into e[8] (cols lane*8.. / 256+lane*8..)
    auto read_row = [&](int buf, int r, float2* e) {
        const float* p = stage + buf * 1024 + r * 256 + lane * 4;
        uint4 d0 = *reinterpret_cast<const uint4*>(p);
        uint4 d1 = *reinterpret_cast<const uint4*>(p + 128);
        cvt8(d0, d1, e);
    };
    auto wait_batches = [&](int b) {   // after this, batch b is resident
        if (b < 7) asm volatile("cp.async.wait_group 1;" ::: "memory");
        else       asm volatile("cp.async.wait_group 0;" ::: "memory");
        __syncwarp();
    };

    float2 e[8];
    float2 vr[8];

    // ---- pass 0: column sums with u == 1 ----
    {
        float2 ca[8];
#pragma unroll
        for (int q = 0; q < 8; ++q) ca[q] = make_float2(0.f, 0.f);
        issue_batch(0);
#pragma unroll
        for (int b = 0; b < 8; ++b) {
            if (b < 7) issue_batch(b + 1);
            wait_batches(b);
#pragma unroll
            for (int r = 0; r < 4; ++r) {
                read_row(b & 1, r, e);
#pragma unroll
                for (int q = 0; q < 8; ++q) { ca[q].x += e[q].x; ca[q].y += e[q].y; }
            }
            __syncwarp();
        }
        float* d0 = scol + w * 512 + lane * 8;
        float* d1 = d0 + 256;
#pragma unroll
        for (int q = 0; q < 4; ++q) {
            d0[2 * q] = ca[q].x;     d0[2 * q + 1] = ca[q].y;
            d1[2 * q] = ca[q + 4].x; d1[2 * q + 1] = ca[q + 4].y;
        }
    }
    __syncthreads();
    {
        float s = c;                         // bin-row contribution, u512 = 1
#pragma unroll
        for (int ww = 0; ww < 16; ++ww) s += scol[ww * 512 + tid];
        sv[tid] = __fdividef(NORM_C, s);
        if (tid == 0) sv[512] = __fdividef(AB512, c * 513.f);
    }
    __syncthreads();
    if (w == 0) {
        float p = 0.f;
#pragma unroll
        for (int k = 0; k < 16; ++k) p += sv[lane + 32 * k];
#pragma unroll
        for (int o = 16; o > 0; o >>= 1) p += __shfl_xor_sync(0xffffffffu, p, o);
        if (lane == 0) sscal[0] = __fdividef(AB512, c * (p + sv[512]));
    }
    __syncthreads();

    // ---- 7 fused passes: row update + next col accumulation, one E read ----
    for (int it = 0; it < 7; ++it) {
#pragma unroll
        for (int q = 0; q < 4; ++q) {
            vr[q]     = *reinterpret_cast<float2*>(&sv[lane * 8 + 2 * q]);
            vr[q + 4] = *reinterpret_cast<float2*>(&sv[256 + lane * 8 + 2 * q]);
        }
        const float v512 = sv[512];
        const float u512 = sscal[0];
        float2 ca[8];
#pragma unroll
        for (int q = 0; q < 8; ++q) ca[q] = make_float2(0.f, 0.f);
        float wsum = 0.f;
        issue_batch(0);
#pragma unroll
        for (int b = 0; b < 8; ++b) {
            if (b < 7) issue_batch(b + 1);
            wait_batches(b);
            float rs[4];
#pragma unroll
            for (int r = 0; r < 4; ++r) {
                read_row(b & 1, r, e);
                float s = 0.f;
#pragma unroll
                for (int q = 0; q < 8; ++q) s += e[q].x * vr[q].x + e[q].y * vr[q].y;
                rs[r] = s;
            }
#pragma unroll
            for (int o = 16; o > 0; o >>= 1) {
#pragma unroll
                for (int r = 0; r < 4; ++r) rs[r] += __shfl_xor_sync(0xffffffffu, rs[r], o);
            }
            float u[4];
#pragma unroll
            for (int r = 0; r < 4; ++r) {
                u[r] = __fdividef(NORM_C, rs[r] + c * v512);
                wsum += u[r];
            }
#pragma unroll
            for (int r = 0; r < 4; ++r) {
                read_row(b & 1, r, e);
#pragma unroll
                for (int q = 0; q < 8; ++q) {
                    ca[q].x += u[r] * e[q].x; ca[q].y += u[r] * e[q].y;
                }
            }
            __syncwarp();
        }
        {
            float* d0 = scol + w * 512 + lane * 8;
            float* d1 = d0 + 256;
#pragma unroll
            for (int q = 0; q < 4; ++q) {
                d0[2 * q] = ca[q].x;     d0[2 * q + 1] = ca[q].y;
                d1[2 * q] = ca[q + 4].x; d1[2 * q + 1] = ca[q + 4].y;
            }
        }
        if (lane == 0) swsum[w] = wsum;
        __syncthreads();
        {
            float s = c * u512;
#pragma unroll
            for (int ww = 0; ww < 16; ++ww) s += scol[ww * 512 + tid];
            sv[tid] = __fdividef(NORM_C, s);
            if (tid == 0) {
                float sU = u512;
#pragma unroll
                for (int ww = 0; ww < 16; ++ww) sU += swsum[ww];
                sv[512] = __fdividef(AB512, c * sU);
            }
        }
        __syncthreads();
        if (w == 0) {
            float p = 0.f;
#pragma unroll
            for (int k = 0; k < 16; ++k) p += sv[lane + 32 * k];
#pragma unroll
            for (int o = 16; o > 0; o >>= 1) p += __shfl_xor_sync(0xffffffffu, p, o);
            if (lane == 0) sscal[0] = __fdividef(AB512, c * (p + sv[512]));
        }
        __syncthreads();
    }

    // ---- final pass: last row update + output write ----
    {
#pragma unroll
        for (int q = 0; q < 4; ++q) {
            vr[q]     = *reinterpret_cast<float2*>(&sv[lane * 8 + 2 * q]);
            vr[q + 4] = *reinterpret_cast<float2*>(&sv[256 + lane * 8 + 2 * q]);
        }
        const float v512 = sv[512];
        const float u512 = sscal[0];
        float* og = out + (size_t)g * MA * MA;
        issue_batch(0);
#pragma unroll
        for (int b = 0; b < 8; ++b) {
            if (b < 7) issue_batch(b + 1);
            wait_batches(b);
            float rs[4];
#pragma unroll
            for (int r = 0; r < 4; ++r) {
                read_row(b & 1, r, e);
                float s = 0.f;
#pragma unroll
                for (int q = 0; q < 8; ++q) s += e[q].x * vr[q].x + e[q].y * vr[q].y;
                rs[r] = s;
            }
#pragma unroll
            for (int o = 16; o > 0; o >>= 1) {
#pragma unroll
                for (int r = 0; r < 4; ++r) rs[r] += __shfl_xor_sync(0xffffffffu, rs[r], o);
            }
#pragma unroll
            for (int r = 0; r < 4; ++r) {
                const int i = row0 + b * 4 + r;
                const float u = __fdividef(NORM_C, rs[r] + c * v512);
                read_row(b & 1, r, e);
                float* o0 = og + (size_t)i * MA + lane * 8;
                float* o1 = o0 + 256;
#pragma unroll
                for (int q = 0; q < 4; ++q) {
                    o0[2 * q]     = u * e[q].x * vr[q].x;
                    o0[2 * q + 1] = u * e[q].y * vr[q].y;
                    o1[2 * q]     = u * e[q + 4].x * vr[q + 4].x;
                    o1[2 * q + 1] = u * e[q + 4].y * vr[q + 4].y;
                }
                if (lane == 0) og[(size_t)i * MA + 512] = u * c * v512;
            }
            __syncwarp();
        }
        og[(size_t)512 * MA + tid] = u512 * c * sv[tid];
        if (tid == 0) og[(size_t)512 * MA + 512] = u512 * c * v512;
    }
}

// ---------------- launch ----------------
extern "C" void kernel_launch(void* const* d_in, const int* in_sizes, int n_in,
                              void* d_out, int out_size) {
    const float* det   = (const float*)d_in[0];
    const float* tra   = (const float*)d_in[1];
    const float* alpha = (const float*)d_in[2];
    const float* eps   = (const float*)d_in[3];
    float* out = (float*)d_out;

    cudaFuncSetAttribute(sinkhorn_kernel, cudaFuncAttributeMaxDynamicSharedMemorySize,
                         SH_FLOATS * (int)sizeof(float));

    normalize_kernel<<<dim3((G_ * M_) / 8, 2), 256>>>(tra, det);
    gemm_kernel<<<dim3(4, 4, G_), 256>>>(eps);
    sinkhorn_kernel<<<G_, 512, SH_FLOATS * sizeof(float)>>>(out, alpha, eps);
}